// round 1
// baseline (speedup 1.0000x reference)
#include <cuda_runtime.h>
#include <cuda_bf16.h>

// NeuralODE: B=131072 trajectories, 149 RK-3/8 steps, f(y)=tanh(y@W1+b1)@W2+b2
// D=2, H=64. One thread per trajectory; weights broadcast from shared memory.

#define NB   131072
#define NSEQ 150
#define ND   2
#define NH   64
#define NPRED 150
#define NSTEPS (NPRED - 1)

// tanh from pre-scaled input p = 2*log2(e)*x :  tanh(x) = 1 - 2/(2^p + 1)
// ex2.approx(+big)=inf -> rcp=0 -> 1 ; ex2.approx(-big)=0 -> 1-2 = -1. Safe at tails.
__device__ __forceinline__ float tanh_from_scaled(float p) {
    float t;
    asm("ex2.approx.f32 %0, %1;" : "=f"(t) : "f"(p));
    float r;
    asm("rcp.approx.f32 %0, %1;" : "=f"(r) : "f"(t + 1.0f));
    return fmaf(-2.0f, r, 1.0f);
}

// One evaluation of f(y). sW1b[j] = {s*W1[0][j], s*W1[1][j], s*b1[j], 0} with s=2*log2e.
// sW2[j] = {W2[j][0], W2[j][1]}.
__device__ __forceinline__ void feval(float y0, float y1,
                                      const float4* __restrict__ sW1b,
                                      const float2* __restrict__ sW2,
                                      float bb0, float bb1,
                                      float& o0, float& o1) {
    float a0 = bb0, a1 = bb1;
#pragma unroll
    for (int j = 0; j < NH; j++) {
        float4 w = sW1b[j];
        float p  = fmaf(y0, w.x, fmaf(y1, w.y, w.z));
        float h  = tanh_from_scaled(p);
        float2 v = sW2[j];
        a0 = fmaf(h, v.x, a0);
        a1 = fmaf(h, v.y, a1);
    }
    o0 = a0; o1 = a1;
}

__global__ void __launch_bounds__(256)
neural_ode_kernel(const float* __restrict__ x,
                  const float* __restrict__ W1,
                  const float* __restrict__ b1,
                  const float* __restrict__ W2,
                  const float* __restrict__ b2,
                  float* __restrict__ out) {
    __shared__ float4 sW1b[NH];
    __shared__ float2 sW2[NH];
    __shared__ float  sb2[2];

    const int tid = threadIdx.x;
    if (tid < NH) {
        const float s = 2.8853900817779268f;  // 2*log2(e)
        sW1b[tid] = make_float4(s * W1[tid], s * W1[NH + tid], s * b1[tid], 0.0f);
        sW2[tid]  = make_float2(W2[2 * tid], W2[2 * tid + 1]);
    }
    if (tid < 2) sb2[tid] = b2[tid];
    __syncthreads();

    const float bb0 = sb2[0];
    const float bb1 = sb2[1];

    const long b = (long)blockIdx.x * blockDim.x + tid;

    // y0 = x[b, SEQ-1, :]
    const float2 yin = *reinterpret_cast<const float2*>(x + b * (long)(NSEQ * ND) + (NSEQ - 1) * ND);
    float y0 = yin.x;
    float y1 = yin.y;

    float2* ob = reinterpret_cast<float2*>(out + b * (long)(NPRED * ND));
    ob[0] = make_float2(y0, y1);

    const float dt   = (float)(150.0 / 149.0);
    const float dt3  = dt * (1.0f / 3.0f);
    const float dt8  = dt * 0.125f;
    const float thrd = 1.0f / 3.0f;

    for (int st = 0; st < NSTEPS; st++) {
        float k1x, k1y, k2x, k2y, k3x, k3y, k4x, k4y;

        // k1 = f(y)
        feval(y0, y1, sW1b, sW2, bb0, bb1, k1x, k1y);
        // k2 = f(y + dt*k1/3)
        feval(fmaf(dt3, k1x, y0), fmaf(dt3, k1y, y1), sW1b, sW2, bb0, bb1, k2x, k2y);
        // k3 = f(y + dt*(k2 - k1/3))
        {
            float i3x = fmaf(dt, k2x - k1x * thrd, y0);
            float i3y = fmaf(dt, k2y - k1y * thrd, y1);
            feval(i3x, i3y, sW1b, sW2, bb0, bb1, k3x, k3y);
        }
        // k4 = f(y + dt*(k1 - k2 + k3))
        {
            float i4x = fmaf(dt, k1x - k2x + k3x, y0);
            float i4y = fmaf(dt, k1y - k2y + k3y, y1);
            feval(i4x, i4y, sW1b, sW2, bb0, bb1, k4x, k4y);
        }
        // y += dt*(k1 + 3*(k2+k3) + k4)/8
        y0 = fmaf(dt8, fmaf(3.0f, k2x + k3x, k1x + k4x), y0);
        y1 = fmaf(dt8, fmaf(3.0f, k2y + k3y, k1y + k4y), y1);

        ob[st + 1] = make_float2(y0, y1);
    }
}

extern "C" void kernel_launch(void* const* d_in, const int* in_sizes, int n_in,
                              void* d_out, int out_size) {
    const float* x  = (const float*)d_in[0];
    const float* W1 = (const float*)d_in[1];
    const float* b1 = (const float*)d_in[2];
    const float* W2 = (const float*)d_in[3];
    const float* b2 = (const float*)d_in[4];
    float* out = (float*)d_out;

    const int block = 256;
    const int grid  = NB / block;  // 512 blocks
    neural_ode_kernel<<<grid, block>>>(x, W1, b1, W2, b2, out);
}

// round 2
// speedup vs baseline: 2.8231x; 2.8231x over previous
#include <cuda_runtime.h>
#include <cuda_bf16.h>

// NeuralODE: B=131072 trajectories, 149 RK-3/8 steps, f(y)=tanh(y@W1+b1)@W2+b2
// D=2, H=64. One thread per trajectory; weights broadcast from shared memory.
//
// R2: occupancy fix (launch_bounds 256,2 -> 16 warps/SM) + batched 8-way MUFU ILP
//     + folded tanh epilogue (a = c - 2*sum(r*w2), r = 1/(exp(2x)+1)).

#define NB   131072
#define NSEQ 150
#define ND   2
#define NH   64
#define NPRED 150
#define NSTEPS (NPRED - 1)

// r = 1/(2^p + 1) with p = 2*log2(e)*x  =>  tanh(x) = 1 - 2r
// ex2.approx(+big)=inf -> rcp=0 -> h=1 ; ex2.approx(-big)=0 -> rcp(1)=1 -> h=-1. Tail-safe.
__device__ __forceinline__ float sigm_r(float p) {
    float t;
    asm("ex2.approx.f32 %0, %1;" : "=f"(t) : "f"(p));
    float r;
    asm("rcp.approx.f32 %0, %1;" : "=f"(r) : "f"(t + 1.0f));
    return r;
}

// One evaluation of f(y). sW1b[j] = {s*W1[0][j], s*W1[1][j], s*b1[j], 0}, s=2*log2e.
// sW2[j] = {W2[j][0], W2[j][1]}. c0/c1 = b2 + colsum(W2).
__device__ __forceinline__ void feval(float y0, float y1,
                                      const float4* __restrict__ sW1b,
                                      const float2* __restrict__ sW2,
                                      float c0, float c1,
                                      float& o0, float& o1) {
    float s0a = 0.0f, s1a = 0.0f, s0b = 0.0f, s1b = 0.0f;
#pragma unroll 1
    for (int j = 0; j < NH; j += 8) {
        // Stage 1: 8 independent pre-activations
        float p[8];
#pragma unroll
        for (int u = 0; u < 8; u++) {
            float4 w = sW1b[j + u];
            p[u] = fmaf(y0, w.x, fmaf(y1, w.y, w.z));
        }
        // Stage 2: 8 independent MUFU chains (pipelined ex2/rcp)
        float r[8];
#pragma unroll
        for (int u = 0; u < 8; u++) {
            r[u] = sigm_r(p[u]);
        }
        // Stage 3: accumulate into 2 independent pairs (short chains)
#pragma unroll
        for (int u = 0; u < 8; u += 2) {
            float2 va = sW2[j + u];
            float2 vb = sW2[j + u + 1];
            s0a = fmaf(r[u],     va.x, s0a);
            s1a = fmaf(r[u],     va.y, s1a);
            s0b = fmaf(r[u + 1], vb.x, s0b);
            s1b = fmaf(r[u + 1], vb.y, s1b);
        }
    }
    o0 = fmaf(-2.0f, s0a + s0b, c0);
    o1 = fmaf(-2.0f, s1a + s1b, c1);
}

__global__ void __launch_bounds__(256, 2)
neural_ode_kernel(const float* __restrict__ x,
                  const float* __restrict__ W1,
                  const float* __restrict__ b1,
                  const float* __restrict__ W2,
                  const float* __restrict__ b2,
                  float* __restrict__ out) {
    __shared__ float4 sW1b[NH];
    __shared__ float2 sW2[NH];
    __shared__ float  sb2[2];

    const int tid = threadIdx.x;
    if (tid < NH) {
        const float s = 2.8853900817779268f;  // 2*log2(e)
        sW1b[tid] = make_float4(s * W1[tid], s * W1[NH + tid], s * b1[tid], 0.0f);
        sW2[tid]  = make_float2(W2[2 * tid], W2[2 * tid + 1]);
    }
    if (tid < 2) sb2[tid] = b2[tid];
    __syncthreads();

    // c = b2 + colsum(W2)   (folds h = 1 - 2r into the epilogue)
    float c0 = sb2[0], c1 = sb2[1];
#pragma unroll
    for (int j = 0; j < NH; j++) {
        float2 v = sW2[j];
        c0 += v.x;
        c1 += v.y;
    }

    const long b = (long)blockIdx.x * blockDim.x + tid;

    // y0 = x[b, SEQ-1, :]
    const float2 yin = *reinterpret_cast<const float2*>(x + b * (long)(NSEQ * ND) + (NSEQ - 1) * ND);
    float y0 = yin.x;
    float y1 = yin.y;

    float2* ob = reinterpret_cast<float2*>(out + b * (long)(NPRED * ND));
    ob[0] = make_float2(y0, y1);

    const float dt   = (float)(150.0 / 149.0);
    const float dt3  = dt * (1.0f / 3.0f);
    const float dt8  = dt * 0.125f;
    const float thrd = 1.0f / 3.0f;

#pragma unroll 1
    for (int st = 0; st < NSTEPS; st++) {
        float k1x, k1y, k2x, k2y, k3x, k3y, k4x, k4y;

        // k1 = f(y)
        feval(y0, y1, sW1b, sW2, c0, c1, k1x, k1y);
        // k2 = f(y + dt*k1/3)
        feval(fmaf(dt3, k1x, y0), fmaf(dt3, k1y, y1), sW1b, sW2, c0, c1, k2x, k2y);
        // k3 = f(y + dt*(k2 - k1/3))
        feval(fmaf(dt, fmaf(-thrd, k1x, k2x), y0),
              fmaf(dt, fmaf(-thrd, k1y, k2y), y1), sW1b, sW2, c0, c1, k3x, k3y);
        // k4 = f(y + dt*(k1 - k2 + k3))
        feval(fmaf(dt, (k1x - k2x) + k3x, y0),
              fmaf(dt, (k1y - k2y) + k3y, y1), sW1b, sW2, c0, c1, k4x, k4y);

        // y += dt*(k1 + 3*(k2+k3) + k4)/8
        y0 = fmaf(dt8, fmaf(3.0f, k2x + k3x, k1x + k4x), y0);
        y1 = fmaf(dt8, fmaf(3.0f, k2y + k3y, k1y + k4y), y1);

        ob[st + 1] = make_float2(y0, y1);
    }
}

extern "C" void kernel_launch(void* const* d_in, const int* in_sizes, int n_in,
                              void* d_out, int out_size) {
    const float* x  = (const float*)d_in[0];
    const float* W1 = (const float*)d_in[1];
    const float* b1 = (const float*)d_in[2];
    const float* W2 = (const float*)d_in[3];
    const float* b2 = (const float*)d_in[4];
    float* out = (float*)d_out;

    const int block = 256;
    const int grid  = NB / block;  // 512 blocks
    neural_ode_kernel<<<grid, block>>>(x, W1, b1, W2, b2, out);
}

// round 3
// speedup vs baseline: 2.9976x; 1.0618x over previous
#include <cuda_runtime.h>
#include <cuda_bf16.h>

// NeuralODE R3: 2 trajectories/thread packed as f32x2, smem weights pre-duplicated
// for splat-free FFMA2 operands, 4-way shared reciprocal (1 rcp per 4 tanh),
// clamped positive sigmoid form r=1/(2^p+1), tanh folded into epilogue c-2*sum(r*v).

#define NB    131072
#define NSEQ  150
#define ND    2
#define NH    64
#define NPRED 150
#define NSTEPS (NPRED - 1)

typedef unsigned long long u64;

__device__ __forceinline__ u64 pk(float a, float b) {
    u64 r; asm("mov.b64 %0, {%1, %2};" : "=l"(r) : "f"(a), "f"(b)); return r;
}
__device__ __forceinline__ float2 upk(u64 v) {
    float2 r; asm("mov.b64 {%0, %1}, %2;" : "=f"(r.x), "=f"(r.y) : "l"(v)); return r;
}
__device__ __forceinline__ u64 fma2(u64 a, u64 b, u64 c) {
    u64 d; asm("fma.rn.f32x2 %0, %1, %2, %3;" : "=l"(d) : "l"(a), "l"(b), "l"(c)); return d;
}
__device__ __forceinline__ u64 add2(u64 a, u64 b) {
    u64 d; asm("add.rn.f32x2 %0, %1, %2;" : "=l"(d) : "l"(a), "l"(b)); return d;
}
__device__ __forceinline__ float ex2f(float p) {
    float t; asm("ex2.approx.f32 %0, %1;" : "=f"(t) : "f"(p)); return t;
}
__device__ __forceinline__ float rcpf(float p) {
    float t; asm("rcp.approx.f32 %0, %1;" : "=f"(t) : "f"(p)); return t;
}

// f(y) for 2 packed trajectories. Processes j in pairs; one rcp serves the
// 4 tanh of (2 traj x 2 j). p clamped <= 31 so u<=2^31+1, 4-product <= 2^124.
__device__ __forceinline__ void feval(u64 y0p, u64 y1p,
                                      const float4* __restrict__ sW,
                                      const float2* __restrict__ sB,
                                      const float4* __restrict__ sV,
                                      u64 c0p, u64 c1p,
                                      u64& o0p, u64& o1p) {
    u64 acc0  = 0ull, acc1  = 0ull;   // {0.f,0.f}
    u64 acc0b = 0ull, acc1b = 0ull;
#pragma unroll 4
    for (int j = 0; j < NH; j += 2) {
        float4 A0  = sW[j];      // {swx,swx,swy,swy} duplicated
        float4 A1  = sW[j + 1];
        float2 Bz0 = sB[j];      // {sb,sb}
        float2 Bz1 = sB[j + 1];
        u64 pA = fma2(y0p, pk(A0.x, A0.y), fma2(y1p, pk(A0.z, A0.w), pk(Bz0.x, Bz0.y)));
        u64 pB = fma2(y0p, pk(A1.x, A1.y), fma2(y1p, pk(A1.z, A1.w), pk(Bz1.x, Bz1.y)));
        float2 a = upk(pA), b = upk(pB);

        float t0 = ex2f(fminf(a.x, 31.0f));
        float t1 = ex2f(fminf(a.y, 31.0f));
        float t2 = ex2f(fminf(b.x, 31.0f));
        float t3 = ex2f(fminf(b.y, 31.0f));
        float u0 = t0 + 1.0f, u1 = t1 + 1.0f;
        float u2 = t2 + 1.0f, u3 = t3 + 1.0f;

        // 4-way shared reciprocal
        float m01 = u0 * u1;
        float m23 = u2 * u3;
        float rc  = rcpf(m01 * m23);
        float rA  = rc * m23;    // = 1/m01
        float rB  = rc * m01;    // = 1/m23
        u64 r01 = pk(rA * u1, rA * u0);   // {r(trajA,j),   r(trajB,j)}
        u64 r23 = pk(rB * u3, rB * u2);   // {r(trajA,j+1), r(trajB,j+1)}

        float4 V0 = sV[j];       // {vx,vx,vy,vy} duplicated
        float4 V1 = sV[j + 1];
        acc0  = fma2(r01, pk(V0.x, V0.y), acc0);
        acc1  = fma2(r01, pk(V0.z, V0.w), acc1);
        acc0b = fma2(r23, pk(V1.x, V1.y), acc0b);
        acc1b = fma2(r23, pk(V1.z, V1.w), acc1b);
    }
    u64 n2 = pk(-2.0f, -2.0f);
    o0p = fma2(n2, add2(acc0, acc0b), c0p);
    o1p = fma2(n2, add2(acc1, acc1b), c1p);
}

__global__ void __launch_bounds__(64, 8)
neural_ode_kernel(const float* __restrict__ x,
                  const float* __restrict__ W1,
                  const float* __restrict__ b1,
                  const float* __restrict__ W2,
                  const float* __restrict__ b2,
                  float* __restrict__ out) {
    __shared__ float4 sW[NH];
    __shared__ float2 sB[NH];
    __shared__ float4 sV[NH];
    __shared__ float  sc[2];

    const int tid = threadIdx.x;
    if (tid < NH) {
        const float s = 2.8853900817779268f;  // 2*log2(e)
        float wx = s * W1[tid], wy = s * W1[NH + tid], bz = s * b1[tid];
        sW[tid] = make_float4(wx, wx, wy, wy);
        sB[tid] = make_float2(bz, bz);
        float vx = W2[2 * tid], vy = W2[2 * tid + 1];
        sV[tid] = make_float4(vx, vx, vy, vy);
    }
    if (tid < 2) {
        float c = b2[tid];
        for (int j = 0; j < NH; j++) c += W2[2 * j + tid];
        sc[tid] = c;
    }
    __syncthreads();

    const u64 c0p = pk(sc[0], sc[0]);
    const u64 c1p = pk(sc[1], sc[1]);

    const long t  = (long)blockIdx.x * blockDim.x + tid;  // 0..65535
    const long bA = 2 * t;
    const long bB = 2 * t + 1;

    float2 ya = *(const float2*)(x + bA * (long)(NSEQ * ND) + (NSEQ - 1) * ND);
    float2 yb = *(const float2*)(x + bB * (long)(NSEQ * ND) + (NSEQ - 1) * ND);
    u64 y0p = pk(ya.x, yb.x);
    u64 y1p = pk(ya.y, yb.y);

    float2* oA = (float2*)(out + bA * (long)(NPRED * ND));
    float2* oB = (float2*)(out + bB * (long)(NPRED * ND));
    {
        float2 p0 = upk(y0p), p1 = upk(y1p);
        oA[0] = make_float2(p0.x, p1.x);
        oB[0] = make_float2(p0.y, p1.y);
    }

    const float dt = (float)(150.0 / 149.0);
    const u64 dtp  = pk(dt, dt);
    const u64 dt3p = pk(dt * (1.0f / 3.0f), dt * (1.0f / 3.0f));
    const u64 dt8p = pk(dt * 0.125f, dt * 0.125f);
    const u64 nthp = pk(-1.0f / 3.0f, -1.0f / 3.0f);
    const u64 n1p  = pk(-1.0f, -1.0f);
    const u64 th3p = pk(3.0f, 3.0f);

#pragma unroll 1
    for (int st = 0; st < NSTEPS; st++) {
        u64 k1x, k1y, k2x, k2y, k3x, k3y, k4x, k4y;

        feval(y0p, y1p, sW, sB, sV, c0p, c1p, k1x, k1y);
        feval(fma2(dt3p, k1x, y0p), fma2(dt3p, k1y, y1p),
              sW, sB, sV, c0p, c1p, k2x, k2y);
        feval(fma2(dtp, fma2(nthp, k1x, k2x), y0p),
              fma2(dtp, fma2(nthp, k1y, k2y), y1p),
              sW, sB, sV, c0p, c1p, k3x, k3y);
        feval(fma2(dtp, add2(fma2(n1p, k2x, k1x), k3x), y0p),
              fma2(dtp, add2(fma2(n1p, k2y, k1y), k3y), y1p),
              sW, sB, sV, c0p, c1p, k4x, k4y);

        y0p = fma2(dt8p, fma2(th3p, add2(k2x, k3x), add2(k1x, k4x)), y0p);
        y1p = fma2(dt8p, fma2(th3p, add2(k2y, k3y), add2(k1y, k4y)), y1p);

        float2 p0 = upk(y0p), p1 = upk(y1p);
        oA[st + 1] = make_float2(p0.x, p1.x);
        oB[st + 1] = make_float2(p0.y, p1.y);
    }
}

extern "C" void kernel_launch(void* const* d_in, const int* in_sizes, int n_in,
                              void* d_out, int out_size) {
    const float* x  = (const float*)d_in[0];
    const float* W1 = (const float*)d_in[1];
    const float* b1 = (const float*)d_in[2];
    const float* W2 = (const float*)d_in[3];
    const float* b2 = (const float*)d_in[4];
    float* out = (float*)d_out;

    const int block = 64;
    const int grid  = (NB / 2) / block;  // 65536 threads -> 1024 CTAs
    neural_ode_kernel<<<grid, block>>>(x, W1, b1, W2, b2, out);
}

// round 4
// speedup vs baseline: 3.2798x; 1.0941x over previous
#include <cuda_runtime.h>
#include <cuda_bf16.h>

// NeuralODE R4: 1 trajectory/thread (4096 warps, high occupancy) + f32x2 packing
// ACROSS the hidden dim (lanes = {j, j+1}) + 4-way shared reciprocal
// (1 rcp per 4 tanh). tanh folded into epilogue: o = c - 2*sum(r*v),
// r = 1/(2^p + 1), p = 2*log2(e)*(y@W1+b1) clamped <= 31.

#define NB    131072
#define NSEQ  150
#define ND    2
#define NH    64
#define NPRED 150
#define NSTEPS (NPRED - 1)

typedef unsigned long long u64;

__device__ __forceinline__ u64 pk(float a, float b) {
    u64 r; asm("mov.b64 %0, {%1, %2};" : "=l"(r) : "f"(a), "f"(b)); return r;
}
__device__ __forceinline__ float2 upk(u64 v) {
    float2 r; asm("mov.b64 {%0, %1}, %2;" : "=f"(r.x), "=f"(r.y) : "l"(v)); return r;
}
__device__ __forceinline__ u64 fma2(u64 a, u64 b, u64 c) {
    u64 d; asm("fma.rn.f32x2 %0, %1, %2, %3;" : "=l"(d) : "l"(a), "l"(b), "l"(c)); return d;
}
__device__ __forceinline__ u64 add2(u64 a, u64 b) {
    u64 d; asm("add.rn.f32x2 %0, %1, %2;" : "=l"(d) : "l"(a), "l"(b)); return d;
}
__device__ __forceinline__ float ex2f(float p) {
    float t; asm("ex2.approx.f32 %0, %1;" : "=f"(t) : "f"(p)); return t;
}
__device__ __forceinline__ float rcpf(float p) {
    float t; asm("rcp.approx.f32 %0, %1;" : "=f"(t) : "f"(p)); return t;
}

// f(y) for one trajectory; hidden units processed 4 at a time (2 lane-pairs).
// sW[jp] = {s*wx_j, s*wx_{j+1}, s*wy_j, s*wy_{j+1}},  sB[jp] = {s*b_j, s*b_{j+1}},
// sV[jp] = {vx_j, vx_{j+1}, vy_j, vy_{j+1}},  s = 2*log2(e).
__device__ __forceinline__ void feval(float y0, float y1,
                                      const float4* __restrict__ sW,
                                      const float2* __restrict__ sB,
                                      const float4* __restrict__ sV,
                                      float c0, float c1,
                                      float& o0, float& o1) {
    const u64 y0p = pk(y0, y0);
    const u64 y1p = pk(y1, y1);
    u64 a0a = 0ull, a1a = 0ull;   // accumulators, lanes = j parity
    u64 a0b = 0ull, a1b = 0ull;
#pragma unroll 4
    for (int jp = 0; jp < NH / 2; jp += 2) {
        float4 W0 = sW[jp];
        float4 W1 = sW[jp + 1];
        float2 B0 = sB[jp];
        float2 B1 = sB[jp + 1];
        u64 pA = fma2(y0p, pk(W0.x, W0.y), fma2(y1p, pk(W0.z, W0.w), pk(B0.x, B0.y)));
        u64 pB = fma2(y0p, pk(W1.x, W1.y), fma2(y1p, pk(W1.z, W1.w), pk(B1.x, B1.y)));
        float2 a = upk(pA), b = upk(pB);

        float t0 = ex2f(fminf(a.x, 31.0f));
        float t1 = ex2f(fminf(a.y, 31.0f));
        float t2 = ex2f(fminf(b.x, 31.0f));
        float t3 = ex2f(fminf(b.y, 31.0f));
        float u0 = t0 + 1.0f, u1 = t1 + 1.0f;
        float u2 = t2 + 1.0f, u3 = t3 + 1.0f;

        // 4-way shared reciprocal: one MUFU rcp serves 4 sigmoids
        float m01 = u0 * u1;
        float m23 = u2 * u3;
        float rc  = rcpf(m01 * m23);
        float rA  = rc * m23;                 // = 1/m01
        float rB  = rc * m01;                 // = 1/m23
        u64 r01 = pk(rA * u1, rA * u0);       // {1/u0, 1/u1}
        u64 r23 = pk(rB * u3, rB * u2);       // {1/u2, 1/u3}

        float4 V0 = sV[jp];
        float4 V1 = sV[jp + 1];
        a0a = fma2(r01, pk(V0.x, V0.y), a0a);
        a1a = fma2(r01, pk(V0.z, V0.w), a1a);
        a0b = fma2(r23, pk(V1.x, V1.y), a0b);
        a1b = fma2(r23, pk(V1.z, V1.w), a1b);
    }
    float2 s0 = upk(add2(a0a, a0b));
    float2 s1 = upk(add2(a1a, a1b));
    o0 = fmaf(-2.0f, s0.x + s0.y, c0);
    o1 = fmaf(-2.0f, s1.x + s1.y, c1);
}

__global__ void __launch_bounds__(128, 7)
neural_ode_kernel(const float* __restrict__ x,
                  const float* __restrict__ W1,
                  const float* __restrict__ b1,
                  const float* __restrict__ W2,
                  const float* __restrict__ b2,
                  float* __restrict__ out) {
    __shared__ float4 sW[NH / 2];
    __shared__ float2 sB[NH / 2];
    __shared__ float4 sV[NH / 2];
    __shared__ float  sc[2];

    const int tid = threadIdx.x;
    if (tid < NH / 2) {
        const float s = 2.8853900817779268f;  // 2*log2(e)
        int j = 2 * tid;
        sW[tid] = make_float4(s * W1[j], s * W1[j + 1],
                              s * W1[NH + j], s * W1[NH + j + 1]);
        sB[tid] = make_float2(s * b1[j], s * b1[j + 1]);
        sV[tid] = make_float4(W2[2 * j], W2[2 * (j + 1)],
                              W2[2 * j + 1], W2[2 * (j + 1) + 1]);
    }
    if (tid < 2) {
        float c = b2[tid];
        for (int j = 0; j < NH; j++) c += W2[2 * j + tid];
        sc[tid] = c;
    }
    __syncthreads();

    const float c0 = sc[0];
    const float c1 = sc[1];

    const long b = (long)blockIdx.x * blockDim.x + tid;

    // y0 = x[b, SEQ-1, :]
    const float2 yin = *(const float2*)(x + b * (long)(NSEQ * ND) + (NSEQ - 1) * ND);
    float y0 = yin.x;
    float y1 = yin.y;

    float2* ob = (float2*)(out + b * (long)(NPRED * ND));
    ob[0] = make_float2(y0, y1);

    const float dt   = (float)(150.0 / 149.0);
    const float dt3  = dt * (1.0f / 3.0f);
    const float dt8  = dt * 0.125f;
    const float thrd = 1.0f / 3.0f;

#pragma unroll 1
    for (int st = 0; st < NSTEPS; st++) {
        float k1x, k1y, k2x, k2y, k3x, k3y, k4x, k4y;

        feval(y0, y1, sW, sB, sV, c0, c1, k1x, k1y);
        feval(fmaf(dt3, k1x, y0), fmaf(dt3, k1y, y1),
              sW, sB, sV, c0, c1, k2x, k2y);
        feval(fmaf(dt, fmaf(-thrd, k1x, k2x), y0),
              fmaf(dt, fmaf(-thrd, k1y, k2y), y1),
              sW, sB, sV, c0, c1, k3x, k3y);
        feval(fmaf(dt, (k1x - k2x) + k3x, y0),
              fmaf(dt, (k1y - k2y) + k3y, y1),
              sW, sB, sV, c0, c1, k4x, k4y);

        y0 = fmaf(dt8, fmaf(3.0f, k2x + k3x, k1x + k4x), y0);
        y1 = fmaf(dt8, fmaf(3.0f, k2y + k3y, k1y + k4y), y1);

        ob[st + 1] = make_float2(y0, y1);
    }
}

extern "C" void kernel_launch(void* const* d_in, const int* in_sizes, int n_in,
                              void* d_out, int out_size) {
    const float* x  = (const float*)d_in[0];
    const float* W1 = (const float*)d_in[1];
    const float* b1 = (const float*)d_in[2];
    const float* W2 = (const float*)d_in[3];
    const float* b2 = (const float*)d_in[4];
    float* out = (float*)d_out;

    const int block = 128;
    const int grid  = NB / block;  // 1024 CTAs, 4096 warps
    neural_ode_kernel<<<grid, block>>>(x, W1, b1, W2, b2, out);
}

// round 5
// speedup vs baseline: 3.4396x; 1.0487x over previous
#include <cuda_runtime.h>
#include <cuda_bf16.h>

// NeuralODE R5: R4's scheme (1 traj/thread, f32x2 across hidden dim, 4-way
// shared reciprocal) with ZERO-MOV operand marshalling: smem weights stored in
// f32x2 lane layout and loaded as u64/ulonglong2 directly into FFMA2 operands.
// regs capped at 64 (8 CTAs/SM).

#define NB    131072
#define NSEQ  150
#define ND    2
#define NH    64
#define NPRED 150
#define NSTEPS (NPRED - 1)

typedef unsigned long long u64;

__device__ __forceinline__ u64 pk(float a, float b) {
    u64 r; asm("mov.b64 %0, {%1, %2};" : "=l"(r) : "f"(a), "f"(b)); return r;
}
__device__ __forceinline__ float2 upk(u64 v) {
    float2 r; asm("mov.b64 {%0, %1}, %2;" : "=f"(r.x), "=f"(r.y) : "l"(v)); return r;
}
__device__ __forceinline__ u64 fma2(u64 a, u64 b, u64 c) {
    u64 d; asm("fma.rn.f32x2 %0, %1, %2, %3;" : "=l"(d) : "l"(a), "l"(b), "l"(c)); return d;
}
__device__ __forceinline__ u64 add2(u64 a, u64 b) {
    u64 d; asm("add.rn.f32x2 %0, %1, %2;" : "=l"(d) : "l"(a), "l"(b)); return d;
}
__device__ __forceinline__ float ex2f(float p) {
    float t; asm("ex2.approx.f32 %0, %1;" : "=f"(t) : "f"(p)); return t;
}
__device__ __forceinline__ float rcpf(float p) {
    float t; asm("rcp.approx.f32 %0, %1;" : "=f"(t) : "f"(p)); return t;
}

// Shared layout (per jp = hidden pair {2jp, 2jp+1}):
//   sWf[jp] = {s*wx_j, s*wx_j1, s*wy_j, s*wy_j1}  -> ulonglong2 {wxp, wyp}
//   sVf[jp] = {vx_j,  vx_j1,  vy_j,  vy_j1}       -> ulonglong2 {vxp, vyp}
//   sBf[jp] = {s*b_j, s*b_j1}                     -> u64 bp
// s = 2*log2(e); tanh folded into epilogue o = c - 2*sum(r*v), r = 1/(2^p+1).
__device__ __forceinline__ void feval(float y0, float y1,
                                      const ulonglong2* __restrict__ sW,
                                      const u64* __restrict__ sB,
                                      const ulonglong2* __restrict__ sV,
                                      float c0, float c1,
                                      float& o0, float& o1) {
    const u64 y0p = pk(y0, y0);
    const u64 y1p = pk(y1, y1);
    u64 a0a = 0ull, a1a = 0ull;
    u64 a0b = 0ull, a1b = 0ull;
#pragma unroll 4
    for (int jp = 0; jp < NH / 2; jp += 2) {
        ulonglong2 W0 = sW[jp];
        ulonglong2 W1 = sW[jp + 1];
        u64 B0 = sB[jp];
        u64 B1 = sB[jp + 1];
        u64 pA = fma2(y0p, W0.x, fma2(y1p, W0.y, B0));
        u64 pB = fma2(y0p, W1.x, fma2(y1p, W1.y, B1));
        float2 a = upk(pA), b = upk(pB);

        float t0 = ex2f(fminf(a.x, 31.0f));
        float t1 = ex2f(fminf(a.y, 31.0f));
        float t2 = ex2f(fminf(b.x, 31.0f));
        float t3 = ex2f(fminf(b.y, 31.0f));
        float u0 = t0 + 1.0f, u1 = t1 + 1.0f;
        float u2 = t2 + 1.0f, u3 = t3 + 1.0f;

        // 4-way shared reciprocal: one MUFU rcp serves 4 sigmoids.
        // p <= 31 -> u <= 2^31+1, 4-product <= ~2^124 (finite).
        float m01 = u0 * u1;
        float m23 = u2 * u3;
        float rc  = rcpf(m01 * m23);
        float rA  = rc * m23;                 // = 1/m01
        float rB  = rc * m01;                 // = 1/m23
        u64 r01 = pk(rA * u1, rA * u0);       // {1/u0, 1/u1}
        u64 r23 = pk(rB * u3, rB * u2);       // {1/u2, 1/u3}

        ulonglong2 V0 = sV[jp];
        ulonglong2 V1 = sV[jp + 1];
        a0a = fma2(r01, V0.x, a0a);
        a1a = fma2(r01, V0.y, a1a);
        a0b = fma2(r23, V1.x, a0b);
        a1b = fma2(r23, V1.y, a1b);
    }
    float2 s0 = upk(add2(a0a, a0b));
    float2 s1 = upk(add2(a1a, a1b));
    o0 = fmaf(-2.0f, s0.x + s0.y, c0);
    o1 = fmaf(-2.0f, s1.x + s1.y, c1);
}

__global__ void __launch_bounds__(128, 8)
neural_ode_kernel(const float* __restrict__ x,
                  const float* __restrict__ W1,
                  const float* __restrict__ b1,
                  const float* __restrict__ W2,
                  const float* __restrict__ b2,
                  float* __restrict__ out) {
    __shared__ alignas(16) float4 sWf[NH / 2];
    __shared__ alignas(16) float4 sVf[NH / 2];
    __shared__ alignas(8)  float2 sBf[NH / 2];
    __shared__ float sc[2];

    const int tid = threadIdx.x;
    if (tid < NH / 2) {
        const float s = 2.8853900817779268f;  // 2*log2(e)
        int j = 2 * tid;
        sWf[tid] = make_float4(s * W1[j], s * W1[j + 1],
                               s * W1[NH + j], s * W1[NH + j + 1]);
        sBf[tid] = make_float2(s * b1[j], s * b1[j + 1]);
        sVf[tid] = make_float4(W2[2 * j], W2[2 * (j + 1)],
                               W2[2 * j + 1], W2[2 * (j + 1) + 1]);
    }
    if (tid < 2) {
        float c = b2[tid];
        for (int j = 0; j < NH; j++) c += W2[2 * j + tid];
        sc[tid] = c;
    }
    __syncthreads();

    const ulonglong2* sW = reinterpret_cast<const ulonglong2*>(sWf);
    const ulonglong2* sV = reinterpret_cast<const ulonglong2*>(sVf);
    const u64*        sB = reinterpret_cast<const u64*>(sBf);

    const float c0 = sc[0];
    const float c1 = sc[1];

    const long b = (long)blockIdx.x * blockDim.x + tid;

    const float2 yin = *(const float2*)(x + b * (long)(NSEQ * ND) + (NSEQ - 1) * ND);
    float y0 = yin.x;
    float y1 = yin.y;

    float2* ob = (float2*)(out + b * (long)(NPRED * ND));
    ob[0] = make_float2(y0, y1);

    const float dt   = (float)(150.0 / 149.0);
    const float dt3  = dt * (1.0f / 3.0f);
    const float dt8  = dt * 0.125f;
    const float thrd = 1.0f / 3.0f;

#pragma unroll 1
    for (int st = 0; st < NSTEPS; st++) {
        float k1x, k1y, k2x, k2y, k3x, k3y, k4x, k4y;

        feval(y0, y1, sW, sB, sV, c0, c1, k1x, k1y);
        feval(fmaf(dt3, k1x, y0), fmaf(dt3, k1y, y1),
              sW, sB, sV, c0, c1, k2x, k2y);
        feval(fmaf(dt, fmaf(-thrd, k1x, k2x), y0),
              fmaf(dt, fmaf(-thrd, k1y, k2y), y1),
              sW, sB, sV, c0, c1, k3x, k3y);
        feval(fmaf(dt, (k1x - k2x) + k3x, y0),
              fmaf(dt, (k1y - k2y) + k3y, y1),
              sW, sB, sV, c0, c1, k4x, k4y);

        y0 = fmaf(dt8, fmaf(3.0f, k2x + k3x, k1x + k4x), y0);
        y1 = fmaf(dt8, fmaf(3.0f, k2y + k3y, k1y + k4y), y1);

        ob[st + 1] = make_float2(y0, y1);
    }
}

extern "C" void kernel_launch(void* const* d_in, const int* in_sizes, int n_in,
                              void* d_out, int out_size) {
    const float* x  = (const float*)d_in[0];
    const float* W1 = (const float*)d_in[1];
    const float* b1 = (const float*)d_in[2];
    const float* W2 = (const float*)d_in[3];
    const float* b2 = (const float*)d_in[4];
    float* out = (float*)d_out;

    const int block = 128;
    const int grid  = NB / block;  // 1024 CTAs, 4096 warps
    neural_ode_kernel<<<grid, block>>>(x, W1, b1, W2, b2, out);
}